// round 10
// baseline (speedup 1.0000x reference)
#include <cuda_runtime.h>
#include <cuda_fp16.h>
#include <stdint.h>
#include <math.h>

// ---------------- problem constants ----------------
#define CDIM    256
#define HDIM    56
#define WDIM    56
#define HW      3136
#define L_TOTAL 25088
#define DDIM    2304

// ---------------- scratch: single fp16 planes ----------------
__device__ __align__(128) __half g_t [(size_t)L_TOTAL * DDIM];
__device__ __align__(128) __half g_h [(size_t)L_TOTAL * CDIM];
__device__ __align__(128) __half g_p [(size_t)L_TOTAL * DDIM];
__device__ __align__(128) __half g_w1[(size_t)CDIM * DDIM];
__device__ __align__(128) __half g_w2[(size_t)DDIM * CDIM];
__device__ __align__(128) __half g_w3[(size_t)CDIM * DDIM];

// ---------------- helpers ----------------
__device__ __forceinline__ uint32_t smem_u32(const void* p) {
    uint32_t a;
    asm("{ .reg .u64 t; cvta.to.shared.u64 t, %1; cvt.u32.u64 %0, t; }" : "=r"(a) : "l"(p));
    return a;
}
__device__ __forceinline__ void ldm_x4(uint32_t* r, uint32_t addr) {
    asm volatile("ldmatrix.sync.aligned.m8n8.x4.shared.b16 {%0,%1,%2,%3}, [%4];"
        : "=r"(r[0]), "=r"(r[1]), "=r"(r[2]), "=r"(r[3]) : "r"(addr));
}
__device__ __forceinline__ void mma16816(float* d, const uint32_t* a, uint32_t b0, uint32_t b1) {
    asm volatile("mma.sync.aligned.m16n8k16.row.col.f32.f16.f16.f32 "
        "{%0,%1,%2,%3}, {%4,%5,%6,%7}, {%8,%9}, {%0,%1,%2,%3};"
        : "+f"(d[0]), "+f"(d[1]), "+f"(d[2]), "+f"(d[3])
        : "r"(a[0]), "r"(a[1]), "r"(a[2]), "r"(a[3]), "r"(b0), "r"(b1));
}
__device__ __forceinline__ void cp_async16(uint32_t dst, const void* src) {
    asm volatile("cp.async.cg.shared.global [%0], [%1], 16;" :: "r"(dst), "l"(src));
}
#define CP_COMMIT() asm volatile("cp.async.commit_group;" ::: "memory")
#define CP_WAIT2()  asm volatile("cp.async.wait_group 2;" ::: "memory")

// ---------------- K0: tiled unfold -> fp16 plane ----------------
__global__ __launch_bounds__(256) void unfold_tiled(const float* __restrict__ x,
    __half* __restrict__ t)
{
    __shared__ __half xs[64 * 3 * 58];
    const int chunk = blockIdx.x;    // 0..3
    const int h     = blockIdx.y;    // 0..55
    const int b     = blockIdx.z;    // 0..7
    const int c0    = chunk * 64;
    const int tid   = threadIdx.x;

    for (int i = tid; i < 64 * 3; i += 256) {
        xs[i * 58 + 0]  = __float2half(0.f);
        xs[i * 58 + 57] = __float2half(0.f);
    }
    for (int i = tid; i < 64 * 3 * 56; i += 256) {
        int w = i % 56;
        int rest = i / 56;
        int hh = rest % 3;
        int c  = rest / 3;
        int gh = h + hh - 1;
        float v = 0.f;
        if (gh >= 0 && gh < HDIM)
            v = x[((size_t)(b * CDIM + c0 + c) * HDIM + gh) * WDIM + w];
        xs[(c * 3 + hh) * 58 + (w + 1)] = __float2half(v);
    }
    __syncthreads();

    const int lbase = b * HW + h * WDIM;
    for (int pid = tid; pid < 56 * 288; pid += 256) {
        int j = pid % 288;
        int w = pid / 288;
        int e0 = 2 * j;
        __half v0, v1;
        {
            int e = e0;
            int c = e / 9, r = e - 9 * c;
            int di = r / 3, dj = r - 3 * di;
            v0 = xs[(c * 3 + di) * 58 + (w + dj)];
        }
        {
            int e = e0 + 1;
            int c = e / 9, r = e - 9 * c;
            int di = r / 3, dj = r - 3 * di;
            v1 = xs[(c * 3 + di) * 58 + (w + dj)];
        }
        __half2 o; o.x = v0; o.y = v1;
        *(__half2*)(t + (size_t)(lbase + w) * DDIM + chunk * 576 + e0) = o;
    }
}

// ---------------- weight transpose: W[K,N] -> fp16 [N,K] ----------------
__global__ __launch_bounds__(256) void wtrans_h(const float* __restrict__ W,
    __half* __restrict__ o, int K, int N)
{
    int t = blockIdx.x * 256 + threadIdx.x;
    int NP = N * (K / 2);
    if (t >= NP) return;
    int kp = t % (K / 2), n = t / (K / 2);
    int k0 = kp * 2;
    __half2 h2;
    h2.x = __float2half(W[(size_t)k0 * N + n]);
    h2.y = __float2half(W[(size_t)(k0 + 1) * N + n]);
    *(__half2*)(o + (size_t)n * K + k0) = h2;
}

// ---------------- pipelined fp16 mma.sync GEMM ----------------
// C = epi(A @ B^T + bias); A [M,K] fp16, B [N,K] fp16. BN = 128 fixed.
// BM template (64 or 128). BK=32, 256 threads, 3-stage cp.async (R8-proven loop shape).
// BM=128: warps 4m x 2n (tile 32x64);  BM=64: warps 2m x 4n (tile 32x32).
// MODE 1: relu -> fp16   MODE 2: sigmoid * X -> fp16   MODE 3: fp32 + bias
#define NSTAGE 3

template<int MODE, int BM>
__global__ __launch_bounds__(256, 2) void gemm_mma(
    const __half* __restrict__ A, const __half* __restrict__ B,
    const float* __restrict__ bias,
    const __half* __restrict__ X,
    __half* __restrict__ Oh, float* __restrict__ Of,
    int M, int N, int Kd)
{
    constexpr int WM   = (BM == 128) ? 4 : 2;   // warps in m
    constexpr int SPAN = (BM == 128) ? 64 : 32; // warp n-span
    constexpr int PB   = SPAN / 16;             // 16-row B groups per warp
    constexpr int TN   = SPAN / 8;              // 8-col n-tiles per warp
    constexpr int ABYTES = BM * 64;             // A plane bytes per stage
    constexpr int BSTAGE = ABYTES + 8192;

    extern __shared__ __align__(128) char smem[];
    const uint32_t sb = smem_u32(smem);

    const int tid  = threadIdx.x;
    const int lane = tid & 31;
    const int wid  = tid >> 5;
    const int warp_m = wid % WM;
    const int warp_n = wid / WM;
    const int m0 = blockIdx.y * BM;
    const int n0 = blockIdx.x * 128;

    const int lr = tid >> 2;          // 0..63
    const int lc = tid & 3;           // 16B chunk 0..3

    float acc[2][TN][4];
    #pragma unroll
    for (int a = 0; a < 2; a++)
        #pragma unroll
        for (int b = 0; b < TN; b++)
            #pragma unroll
            for (int c = 0; c < 4; c++) acc[a][b][c] = 0.f;

    // ldmatrix per-lane addressing (64B rows, chunk swizzle c ^ ((r>>1)&3))
    const int grp = lane >> 3, r8 = lane & 7;
    const int rowoff = ((grp & 1) << 3) + r8;
    const int cg = grp >> 1;
    int offA[2], swA[2], offB[PB], swB[PB];
    #pragma unroll
    for (int tm = 0; tm < 2; tm++) {
        int r = warp_m * 32 + tm * 16 + rowoff;
        offA[tm] = r * 64; swA[tm] = (r >> 1) & 3;
    }
    #pragma unroll
    for (int p = 0; p < PB; p++) {
        int r = warp_n * SPAN + p * 16 + rowoff;
        offB[p] = r * 64; swB[p] = (r >> 1) & 3;
    }

    const int NIT = Kd >> 5;

    auto load_stage = [&](int st, int k0) {
        uint32_t stb = sb + st * BSTAGE;
        #pragma unroll
        for (int i = 0; i < BM / 64; i++) {
            int r = (i << 6) + lr;
            uint32_t dst = stb + r * 64 + ((lc ^ ((r >> 1) & 3)) << 4);
            cp_async16(dst, (const char*)(A + (size_t)(m0 + r) * Kd + k0 + lc * 8));
        }
        #pragma unroll
        for (int i = 0; i < 2; i++) {
            int r = (i << 6) + lr;
            uint32_t dst = stb + ABYTES + r * 64 + ((lc ^ ((r >> 1) & 3)) << 4);
            cp_async16(dst, (const char*)(B + (size_t)(n0 + r) * Kd + k0 + lc * 8));
        }
    };

    #pragma unroll
    for (int s = 0; s < NSTAGE; s++) {
        load_stage(s, s * 32);
        CP_COMMIT();
    }

    for (int it = 0; it < NIT; it++) {
        CP_WAIT2();
        __syncthreads();
        const int st = it % NSTAGE;
        const uint32_t stb = sb + st * BSTAGE;

        #pragma unroll
        for (int ks = 0; ks < 2; ks++) {
            uint32_t ah[2][4], bh[PB][4];
            #pragma unroll
            for (int tm = 0; tm < 2; tm++) {
                uint32_t colA = (uint32_t)((((ks << 1) | cg) ^ swA[tm]) << 4);
                ldm_x4(ah[tm], stb + offA[tm] + colA);
            }
            #pragma unroll
            for (int p = 0; p < PB; p++) {
                uint32_t colB = (uint32_t)((((ks << 1) | cg) ^ swB[p]) << 4);
                ldm_x4(bh[p], stb + ABYTES + offB[p] + colB);
            }
            #pragma unroll
            for (int tm = 0; tm < 2; tm++)
                #pragma unroll
                for (int tn = 0; tn < TN; tn++) {
                    int p = tn >> 1, o = tn & 1;
                    mma16816(acc[tm][tn], ah[tm], bh[p][o], bh[p][2 + o]);
                }
        }
        __syncthreads();

        int nxt = it + NSTAGE;
        if (nxt < NIT) load_stage(st, nxt * 32);
        CP_COMMIT();
    }

    // ---------------- epilogue ----------------
    const int qr = lane >> 2;
    const int qc = (lane & 3) * 2;
    #pragma unroll
    for (int tm = 0; tm < 2; tm++) {
        int mb = m0 + warp_m * 32 + tm * 16;
        #pragma unroll
        for (int tn = 0; tn < TN; tn++) {
            int n = n0 + warp_n * SPAN + tn * 8 + qc;
            float bx = bias[n], by = bias[n + 1];
            #pragma unroll
            for (int half = 0; half < 2; half++) {
                int m = mb + qr + half * 8;
                float vx = acc[tm][tn][half * 2 + 0] + bx;
                float vy = acc[tm][tn][half * 2 + 1] + by;
                size_t o = (size_t)m * N + n;
                if (MODE == 1) {
                    __half2 w;
                    w.x = __float2half(fmaxf(vx, 0.f));
                    w.y = __float2half(fmaxf(vy, 0.f));
                    *(__half2*)(Oh + o) = w;
                } else if (MODE == 2) {
                    float sx = 1.f / (1.f + __expf(-vx));
                    float sy = 1.f / (1.f + __expf(-vy));
                    __half2 tv = *(const __half2*)(X + o);
                    __half2 w;
                    w.x = __float2half(__half2float(tv.x) * sx);
                    w.y = __float2half(__half2float(tv.y) * sy);
                    *(__half2*)(Oh + o) = w;
                } else {
                    float2 w; w.x = vx; w.y = vy;
                    *(float2*)(Of + o) = w;
                }
            }
        }
    }
}

// ---------------- host launch ----------------
extern "C" void kernel_launch(void* const* d_in, const int* in_sizes, int n_in,
                              void* d_out, int out_size)
{
    const float* x  = (const float*)d_in[0];
    const float* W1 = (const float*)d_in[1];
    const float* b1 = (const float*)d_in[2];
    const float* W2 = (const float*)d_in[3];
    const float* b2 = (const float*)d_in[4];
    const float* W3 = (const float*)d_in[5];
    const float* b3 = (const float*)d_in[6];
    float* out = (float*)d_out;

    __half *pt, *ph, *pp, *w1, *w2, *w3;
    cudaGetSymbolAddress((void**)&pt, g_t);
    cudaGetSymbolAddress((void**)&ph, g_h);
    cudaGetSymbolAddress((void**)&pp, g_p);
    cudaGetSymbolAddress((void**)&w1, g_w1);
    cudaGetSymbolAddress((void**)&w2, g_w2);
    cudaGetSymbolAddress((void**)&w3, g_w3);

    const int SM64  = NSTAGE * (64 * 64 + 8192);    // 36864
    const int SM128 = NSTAGE * (128 * 64 + 8192);   // 49152
    cudaFuncSetAttribute(gemm_mma<1, 64>,  cudaFuncAttributeMaxDynamicSharedMemorySize, SM64);
    cudaFuncSetAttribute(gemm_mma<2, 128>, cudaFuncAttributeMaxDynamicSharedMemorySize, SM128);
    cudaFuncSetAttribute(gemm_mma<3, 64>,  cudaFuncAttributeMaxDynamicSharedMemorySize, SM64);

    unfold_tiled<<<dim3(4, 56, 8), 256>>>(x, pt);
    wtrans_h<<<(CDIM * (DDIM / 2) + 255) / 256, 256>>>(W1, w1, DDIM, CDIM);
    wtrans_h<<<(DDIM * (CDIM / 2) + 255) / 256, 256>>>(W2, w2, CDIM, DDIM);
    wtrans_h<<<(CDIM * (DDIM / 2) + 255) / 256, 256>>>(W3, w3, DDIM, CDIM);

    // K1: h = relu(t @ W1 + b1)        [25088 x 256],  K=2304, BM=64
    gemm_mma<1, 64><<<dim3(CDIM / 128, L_TOTAL / 64), 256, SM64>>>(
        pt, w1, b1, nullptr, ph, nullptr, L_TOTAL, CDIM, DDIM);
    // K2: p = t * sigmoid(h @ W2 + b2) [25088 x 2304], K=256, BM=128
    gemm_mma<2, 128><<<dim3(DDIM / 128, L_TOTAL / 128), 256, SM128>>>(
        ph, w2, b2, pt, pp, nullptr, L_TOTAL, DDIM, CDIM);
    // K3: out = p @ W3 + b3            [25088 x 256],  K=2304, BM=64
    gemm_mma<3, 64><<<dim3(CDIM / 128, L_TOTAL / 64), 256, SM64>>>(
        pp, w3, b3, nullptr, nullptr, out, L_TOTAL, CDIM, DDIM);
}

// round 11
// speedup vs baseline: 1.0262x; 1.0262x over previous
#include <cuda_runtime.h>
#include <cuda_fp16.h>
#include <stdint.h>
#include <math.h>

// ---------------- problem constants ----------------
#define CDIM    256
#define HDIM    56
#define WDIM    56
#define HW      3136
#define L_TOTAL 25088
#define DDIM    2304

// ---------------- scratch ----------------
__device__ __align__(128) __half g_t [(size_t)L_TOTAL * DDIM];
__device__ __align__(128) __half g_h [(size_t)L_TOTAL * CDIM];
__device__ __align__(128) __half g_p [(size_t)L_TOTAL * DDIM];
__device__ __align__(128) __half g_w1[(size_t)CDIM * DDIM];
__device__ __align__(128) __half g_w2[(size_t)DDIM * CDIM];
__device__ __align__(128) __half g_w3[(size_t)CDIM * DDIM];
__device__ __align__(128) float  g_part[2 * (size_t)L_TOTAL * CDIM];  // split-K partials

// ---------------- helpers ----------------
__device__ __forceinline__ uint32_t smem_u32(const void* p) {
    uint32_t a;
    asm("{ .reg .u64 t; cvta.to.shared.u64 t, %1; cvt.u32.u64 %0, t; }" : "=r"(a) : "l"(p));
    return a;
}
__device__ __forceinline__ void ldm_x4(uint32_t* r, uint32_t addr) {
    asm volatile("ldmatrix.sync.aligned.m8n8.x4.shared.b16 {%0,%1,%2,%3}, [%4];"
        : "=r"(r[0]), "=r"(r[1]), "=r"(r[2]), "=r"(r[3]) : "r"(addr));
}
__device__ __forceinline__ void mma16816(float* d, const uint32_t* a, uint32_t b0, uint32_t b1) {
    asm volatile("mma.sync.aligned.m16n8k16.row.col.f32.f16.f16.f32 "
        "{%0,%1,%2,%3}, {%4,%5,%6,%7}, {%8,%9}, {%0,%1,%2,%3};"
        : "+f"(d[0]), "+f"(d[1]), "+f"(d[2]), "+f"(d[3])
        : "r"(a[0]), "r"(a[1]), "r"(a[2]), "r"(a[3]), "r"(b0), "r"(b1));
}
__device__ __forceinline__ void cp_async16(uint32_t dst, const void* src) {
    asm volatile("cp.async.cg.shared.global [%0], [%1], 16;" :: "r"(dst), "l"(src));
}
#define CP_COMMIT() asm volatile("cp.async.commit_group;" ::: "memory")
#define CP_WAIT2()  asm volatile("cp.async.wait_group 2;" ::: "memory")

// ---------------- K0: unfold -> fp16 plane (R8-proven) ----------------
__global__ __launch_bounds__(256) void unfold_h(const float* __restrict__ x,
    __half* __restrict__ t)
{
    long long pidx = (long long)blockIdx.x * 256 + threadIdx.x;
    const long long NP = (long long)L_TOTAL * (DDIM / 2);
    if (pidx >= NP) return;
    int dp = (int)(pidx % (DDIM / 2));
    int l  = (int)(pidx / (DDIM / 2));
    int d0 = dp * 2;
    int b = l / HW, p = l % HW;
    int h = p / WDIM, w = p % WDIM;
    float v[2];
    #pragma unroll
    for (int j = 0; j < 2; j++) {
        int d = d0 + j;
        int c = d / 9, r = d % 9;
        int hh = h + r / 3 - 1, ww = w + r % 3 - 1;
        float vv = 0.f;
        if (hh >= 0 && hh < HDIM && ww >= 0 && ww < WDIM)
            vv = x[((b * CDIM + c) * HDIM + hh) * WDIM + ww];
        v[j] = vv;
    }
    __half2 h2; h2.x = __float2half(v[0]); h2.y = __float2half(v[1]);
    *(__half2*)(t + (size_t)l * DDIM + d0) = h2;
}

// ---------------- weight transpose: W[K,N] -> fp16 [N,K] ----------------
__global__ __launch_bounds__(256) void wtrans_h(const float* __restrict__ W,
    __half* __restrict__ o, int K, int N)
{
    int t = blockIdx.x * 256 + threadIdx.x;
    int NP = N * (K / 2);
    if (t >= NP) return;
    int kp = t % (K / 2), n = t / (K / 2);
    int k0 = kp * 2;
    __half2 h2;
    h2.x = __float2half(W[(size_t)k0 * N + n]);
    h2.y = __float2half(W[(size_t)(k0 + 1) * N + n]);
    *(__half2*)(o + (size_t)n * K + k0) = h2;
}

// ---------------- split-K combine kernels ----------------
// h = relu(p0 + p1 + bias) -> fp16   (CDIM columns)
__global__ __launch_bounds__(256) void combine_relu(const float* __restrict__ part,
    const float* __restrict__ bias, __half* __restrict__ out)
{
    int idx = blockIdx.x * 256 + threadIdx.x;           // float4 index
    const int TOT = L_TOTAL * CDIM / 4;
    if (idx >= TOT) return;
    int col4 = (idx % (CDIM / 4)) * 4;
    float4 a = *(const float4*)(part + (size_t)idx * 4);
    float4 b = *(const float4*)(part + (size_t)L_TOTAL * CDIM + (size_t)idx * 4);
    float4 bs = *(const float4*)(bias + col4);
    __half2 o0, o1;
    o0.x = __float2half(fmaxf(a.x + b.x + bs.x, 0.f));
    o0.y = __float2half(fmaxf(a.y + b.y + bs.y, 0.f));
    o1.x = __float2half(fmaxf(a.z + b.z + bs.z, 0.f));
    o1.y = __float2half(fmaxf(a.w + b.w + bs.w, 0.f));
    *(__half2*)(out + (size_t)idx * 4)     = o0;
    *(__half2*)(out + (size_t)idx * 4 + 2) = o1;
}

// out = p0 + p1 + bias -> fp32
__global__ __launch_bounds__(256) void combine_bias(const float* __restrict__ part,
    const float* __restrict__ bias, float* __restrict__ out)
{
    int idx = blockIdx.x * 256 + threadIdx.x;
    const int TOT = L_TOTAL * CDIM / 4;
    if (idx >= TOT) return;
    int col4 = (idx % (CDIM / 4)) * 4;
    float4 a = *(const float4*)(part + (size_t)idx * 4);
    float4 b = *(const float4*)(part + (size_t)L_TOTAL * CDIM + (size_t)idx * 4);
    float4 bs = *(const float4*)(bias + col4);
    float4 o;
    o.x = a.x + b.x + bs.x; o.y = a.y + b.y + bs.y;
    o.z = a.z + b.z + bs.z; o.w = a.w + b.w + bs.w;
    *(float4*)(out + (size_t)idx * 4) = o;
}

// ---------------- pipelined fp16 mma.sync GEMM (R8 shape) ----------------
// C = epi(A @ B^T [+ bias]); A [M,Kstride] fp16, B [N,Kstride] fp16.
// BM=128 BN=128 BK=32, 256 threads, 3-stage cp.async, warps 4m x 2n.
// Klen = K handled per CTA; blockIdx.z = split index (k offset z*Klen, partial plane z).
// MODE 0: fp32 partial (no bias)   MODE 2: sigmoid * X -> fp16 (+bias)
#define STAGE_B 16384
#define NSTAGE  3
#define SMEM_BYTES (NSTAGE * STAGE_B)

template<int MODE>
__global__ __launch_bounds__(256, 2) void gemm_mma(
    const __half* __restrict__ A, const __half* __restrict__ B,
    const float* __restrict__ bias,
    const __half* __restrict__ X,
    __half* __restrict__ Oh, float* __restrict__ Of,
    int M, int N, int Kstride, int Klen)
{
    extern __shared__ __align__(128) char smem[];
    const uint32_t sb = smem_u32(smem);

    const int tid  = threadIdx.x;
    const int lane = tid & 31;
    const int wid  = tid >> 5;
    const int warp_m = wid & 3;
    const int warp_n = wid >> 2;
    const int m0 = blockIdx.y * 128;
    const int n0 = blockIdx.x * 128;
    const int koff = blockIdx.z * Klen;

    const int lr = tid >> 2;
    const int lc = tid & 3;

    float acc[2][8][4];
    #pragma unroll
    for (int a = 0; a < 2; a++)
        #pragma unroll
        for (int b = 0; b < 8; b++)
            #pragma unroll
            for (int c = 0; c < 4; c++) acc[a][b][c] = 0.f;

    const int grp = lane >> 3, r8 = lane & 7;
    const int rowoff = ((grp & 1) << 3) + r8;
    const int cg = grp >> 1;
    int offA[2], swA[2], offB[4], swB[4];
    #pragma unroll
    for (int tm = 0; tm < 2; tm++) {
        int r = warp_m * 32 + tm * 16 + rowoff;
        offA[tm] = r * 64; swA[tm] = (r >> 1) & 3;
    }
    #pragma unroll
    for (int p = 0; p < 4; p++) {
        int r = warp_n * 64 + p * 16 + rowoff;
        offB[p] = r * 64; swB[p] = (r >> 1) & 3;
    }

    const int NIT = Klen >> 5;

    auto load_stage = [&](int st, int k0) {
        uint32_t stb = sb + st * STAGE_B;
        #pragma unroll
        for (int i = 0; i < 4; i++) {
            int plane = i >> 1;
            int r = ((i & 1) << 6) + lr;
            uint32_t dst = stb + plane * 8192 + r * 64 + ((lc ^ ((r >> 1) & 3)) << 4);
            const char* src = (plane == 0)
                ? (const char*)(A + (size_t)(m0 + r) * Kstride + koff + k0 + lc * 8)
                : (const char*)(B + (size_t)(n0 + r) * Kstride + koff + k0 + lc * 8);
            cp_async16(dst, src);
        }
    };

    #pragma unroll
    for (int s = 0; s < NSTAGE; s++) {
        load_stage(s, s * 32);
        CP_COMMIT();
    }

    for (int it = 0; it < NIT; it++) {
        CP_WAIT2();
        __syncthreads();
        const int st = it % NSTAGE;
        const uint32_t stb = sb + st * STAGE_B;

        #pragma unroll
        for (int ks = 0; ks < 2; ks++) {
            uint32_t ah[2][4], bh[4][4];
            #pragma unroll
            for (int tm = 0; tm < 2; tm++) {
                uint32_t colA = (uint32_t)((((ks << 1) | cg) ^ swA[tm]) << 4);
                ldm_x4(ah[tm], stb + offA[tm] + colA);
            }
            #pragma unroll
            for (int p = 0; p < 4; p++) {
                uint32_t colB = (uint32_t)((((ks << 1) | cg) ^ swB[p]) << 4);
                ldm_x4(bh[p], stb + 8192 + offB[p] + colB);
            }
            #pragma unroll
            for (int tm = 0; tm < 2; tm++)
                #pragma unroll
                for (int tn = 0; tn < 8; tn++) {
                    int p = tn >> 1, o = tn & 1;
                    mma16816(acc[tm][tn], ah[tm], bh[p][o], bh[p][2 + o]);
                }
        }
        __syncthreads();

        int nxt = it + NSTAGE;
        if (nxt < NIT) load_stage(st, nxt * 32);
        CP_COMMIT();
    }

    // ---------------- epilogue ----------------
    float* Ofz = Of + (size_t)blockIdx.z * M * N;   // partial plane (MODE 0)
    const int qr = lane >> 2;
    const int qc = (lane & 3) * 2;
    #pragma unroll
    for (int tm = 0; tm < 2; tm++) {
        int mb = m0 + warp_m * 32 + tm * 16;
        #pragma unroll
        for (int tn = 0; tn < 8; tn++) {
            int n = n0 + warp_n * 64 + tn * 8 + qc;
            #pragma unroll
            for (int half = 0; half < 2; half++) {
                int m = mb + qr + half * 8;
                float vx = acc[tm][tn][half * 2 + 0];
                float vy = acc[tm][tn][half * 2 + 1];
                size_t o = (size_t)m * N + n;
                if (MODE == 0) {
                    float2 w; w.x = vx; w.y = vy;
                    *(float2*)(Ofz + o) = w;
                } else if (MODE == 2) {
                    vx += bias[n]; vy += bias[n + 1];
                    float sx = 1.f / (1.f + __expf(-vx));
                    float sy = 1.f / (1.f + __expf(-vy));
                    __half2 tv = *(const __half2*)(X + o);
                    __half2 w;
                    w.x = __float2half(__half2float(tv.x) * sx);
                    w.y = __float2half(__half2float(tv.y) * sy);
                    *(__half2*)(Oh + o) = w;
                }
            }
        }
    }
}

// ---------------- host launch ----------------
extern "C" void kernel_launch(void* const* d_in, const int* in_sizes, int n_in,
                              void* d_out, int out_size)
{
    const float* x  = (const float*)d_in[0];
    const float* W1 = (const float*)d_in[1];
    const float* b1 = (const float*)d_in[2];
    const float* W2 = (const float*)d_in[3];
    const float* b2 = (const float*)d_in[4];
    const float* W3 = (const float*)d_in[5];
    const float* b3 = (const float*)d_in[6];
    float* out = (float*)d_out;

    __half *pt, *ph, *pp, *w1, *w2, *w3;
    float* ppart;
    cudaGetSymbolAddress((void**)&pt, g_t);
    cudaGetSymbolAddress((void**)&ph, g_h);
    cudaGetSymbolAddress((void**)&pp, g_p);
    cudaGetSymbolAddress((void**)&w1, g_w1);
    cudaGetSymbolAddress((void**)&w2, g_w2);
    cudaGetSymbolAddress((void**)&w3, g_w3);
    cudaGetSymbolAddress((void**)&ppart, g_part);

    cudaFuncSetAttribute(gemm_mma<0>, cudaFuncAttributeMaxDynamicSharedMemorySize, SMEM_BYTES);
    cudaFuncSetAttribute(gemm_mma<2>, cudaFuncAttributeMaxDynamicSharedMemorySize, SMEM_BYTES);

    long long np = (long long)L_TOTAL * (DDIM / 2);
    unfold_h<<<(unsigned)((np + 255) / 256), 256>>>(x, pt);
    wtrans_h<<<(CDIM * (DDIM / 2) + 255) / 256, 256>>>(W1, w1, DDIM, CDIM);
    wtrans_h<<<(DDIM * (CDIM / 2) + 255) / 256, 256>>>(W2, w2, CDIM, DDIM);
    wtrans_h<<<(CDIM * (DDIM / 2) + 255) / 256, 256>>>(W3, w3, DDIM, CDIM);

    const int CGRID = (L_TOTAL * CDIM / 4 + 255) / 256;

    // K1: partials = t @ W1 (split-K 2), then h = relu(sum + b1)
    gemm_mma<0><<<dim3(CDIM / 128, L_TOTAL / 128, 2), 256, SMEM_BYTES>>>(
        pt, w1, nullptr, nullptr, nullptr, ppart, L_TOTAL, CDIM, DDIM, DDIM / 2);
    combine_relu<<<CGRID, 256>>>(ppart, b1, ph);

    // K2: p = t * sigmoid(h @ W2 + b2)  [25088 x 2304], K=256 (no split)
    gemm_mma<2><<<dim3(DDIM / 128, L_TOTAL / 128, 1), 256, SMEM_BYTES>>>(
        ph, w2, b2, pt, pp, nullptr, L_TOTAL, DDIM, CDIM, CDIM);

    // K3: partials = p @ W3 (split-K 2), then out = sum + b3
    gemm_mma<0><<<dim3(CDIM / 128, L_TOTAL / 128, 2), 256, SMEM_BYTES>>>(
        pp, w3, nullptr, nullptr, nullptr, ppart, L_TOTAL, CDIM, DDIM, DDIM / 2);
    combine_bias<<<CGRID, 256>>>(ppart, b3, out);
}

// round 12
// speedup vs baseline: 1.0719x; 1.0445x over previous
#include <cuda_runtime.h>
#include <cuda_fp16.h>
#include <stdint.h>
#include <math.h>

// ---------------- problem constants ----------------
#define CDIM    256
#define HDIM    56
#define WDIM    56
#define HW      3136
#define L_TOTAL 25088
#define DDIM    2304

// ---------------- scratch: single fp16 planes ----------------
__device__ __align__(128) __half g_t [(size_t)L_TOTAL * DDIM];
__device__ __align__(128) __half g_h [(size_t)L_TOTAL * CDIM];
__device__ __align__(128) __half g_p [(size_t)L_TOTAL * DDIM];
__device__ __align__(128) __half g_w1[(size_t)CDIM * DDIM];
__device__ __align__(128) __half g_w2[(size_t)DDIM * CDIM];
__device__ __align__(128) __half g_w3[(size_t)CDIM * DDIM];

// ---------------- helpers ----------------
__device__ __forceinline__ uint32_t smem_u32(const void* p) {
    uint32_t a;
    asm("{ .reg .u64 t; cvta.to.shared.u64 t, %1; cvt.u32.u64 %0, t; }" : "=r"(a) : "l"(p));
    return a;
}
__device__ __forceinline__ void ldm_x4(uint32_t* r, uint32_t addr) {
    asm volatile("ldmatrix.sync.aligned.m8n8.x4.shared.b16 {%0,%1,%2,%3}, [%4];"
        : "=r"(r[0]), "=r"(r[1]), "=r"(r[2]), "=r"(r[3]) : "r"(addr));
}
__device__ __forceinline__ void mma16816(float* d, const uint32_t* a, uint32_t b0, uint32_t b1) {
    asm volatile("mma.sync.aligned.m16n8k16.row.col.f32.f16.f16.f32 "
        "{%0,%1,%2,%3}, {%4,%5,%6,%7}, {%8,%9}, {%0,%1,%2,%3};"
        : "+f"(d[0]), "+f"(d[1]), "+f"(d[2]), "+f"(d[3])
        : "r"(a[0]), "r"(a[1]), "r"(a[2]), "r"(a[3]), "r"(b0), "r"(b1));
}
__device__ __forceinline__ void cp_async16(uint32_t dst, const void* src) {
    asm volatile("cp.async.cg.shared.global [%0], [%1], 16;" :: "r"(dst), "l"(src));
}
#define CP_COMMIT() asm volatile("cp.async.commit_group;" ::: "memory")
#define CP_WAIT2()  asm volatile("cp.async.wait_group 2;" ::: "memory")

// ---------------- K0: tiled unfold -> fp16 plane (bit-identical to unfold_h) ----------------
// grid (4 c-chunks, 56 h, 8 b), 256 threads. smem tile of x: [64c][3hh][58ww padded].
__global__ __launch_bounds__(256) void unfold_tiled(const float* __restrict__ x,
    __half* __restrict__ t)
{
    __shared__ __half xs[64 * 3 * 58];
    const int chunk = blockIdx.x;    // 0..3
    const int h     = blockIdx.y;    // 0..55
    const int b     = blockIdx.z;    // 0..7
    const int c0    = chunk * 64;
    const int tid   = threadIdx.x;

    for (int i = tid; i < 64 * 3; i += 256) {
        xs[i * 58 + 0]  = __float2half(0.f);
        xs[i * 58 + 57] = __float2half(0.f);
    }
    for (int i = tid; i < 64 * 3 * 56; i += 256) {
        int w = i % 56;
        int rest = i / 56;
        int hh = rest % 3;
        int c  = rest / 3;
        int gh = h + hh - 1;
        float v = 0.f;
        if (gh >= 0 && gh < HDIM)
            v = x[((size_t)(b * CDIM + c0 + c) * HDIM + gh) * WDIM + w];
        xs[(c * 3 + hh) * 58 + (w + 1)] = __float2half(v);
    }
    __syncthreads();

    const int lbase = b * HW + h * WDIM;
    for (int pid = tid; pid < 56 * 288; pid += 256) {
        int j = pid % 288;
        int w = pid / 288;
        int e0 = 2 * j;
        __half v0, v1;
        {
            int e = e0;
            int c = e / 9, r = e - 9 * c;
            int di = r / 3, dj = r - 3 * di;
            v0 = xs[(c * 3 + di) * 58 + (w + dj)];
        }
        {
            int e = e0 + 1;
            int c = e / 9, r = e - 9 * c;
            int di = r / 3, dj = r - 3 * di;
            v1 = xs[(c * 3 + di) * 58 + (w + dj)];
        }
        __half2 o; o.x = v0; o.y = v1;
        *(__half2*)(t + (size_t)(lbase + w) * DDIM + chunk * 576 + e0) = o;
    }
}

// ---------------- fused weight transpose: all three W[K,N] -> fp16 [N,K] ----------------
// 1152 blocks per segment; segment 0: W1 (K=2304,N=256), 1: W2 (K=256,N=2304), 2: W3.
__global__ __launch_bounds__(256) void wtrans_all(
    const float* __restrict__ W1, const float* __restrict__ W2, const float* __restrict__ W3,
    __half* __restrict__ o1, __half* __restrict__ o2, __half* __restrict__ o3)
{
    const int seg = blockIdx.x / 1152;
    const int blk = blockIdx.x % 1152;
    const float* W = (seg == 0) ? W1 : (seg == 1) ? W2 : W3;
    __half* o      = (seg == 0) ? o1 : (seg == 1) ? o2 : o3;
    const int K    = (seg == 1) ? CDIM : DDIM;
    const int N    = (seg == 1) ? DDIM : CDIM;

    int t = blk * 256 + threadIdx.x;
    int NP = N * (K / 2);
    if (t >= NP) return;
    int kp = t % (K / 2), n = t / (K / 2);
    int k0 = kp * 2;
    __half2 h2;
    h2.x = __float2half(W[(size_t)k0 * N + n]);
    h2.y = __float2half(W[(size_t)(k0 + 1) * N + n]);
    *(__half2*)(o + (size_t)n * K + k0) = h2;
}

// ---------------- pipelined fp16 mma.sync GEMM (R8-exact) ----------------
// C = epi(A @ B^T + bias); A [M,K] fp16, B [N,K] fp16.
// BM=128 BN=128 BK=32, 256 threads, 3-stage cp.async pipeline, warps 4m x 2n.
// MODE 1: relu -> fp16   MODE 2: sigmoid * X -> fp16   MODE 3: fp32 + bias
#define STAGE_B 16384
#define NSTAGE  3
#define SMEM_BYTES (NSTAGE * STAGE_B)

template<int MODE>
__global__ __launch_bounds__(256, 2) void gemm_mma(
    const __half* __restrict__ A, const __half* __restrict__ B,
    const float* __restrict__ bias,
    const __half* __restrict__ X,
    __half* __restrict__ Oh, float* __restrict__ Of,
    int M, int N, int Kd)
{
    extern __shared__ __align__(128) char smem[];
    const uint32_t sb = smem_u32(smem);

    const int tid  = threadIdx.x;
    const int lane = tid & 31;
    const int wid  = tid >> 5;
    const int warp_m = wid & 3;
    const int warp_n = wid >> 2;
    const int m0 = blockIdx.y * 128;
    const int n0 = blockIdx.x * 128;

    const int lr = tid >> 2;
    const int lc = tid & 3;

    float acc[2][8][4];
    #pragma unroll
    for (int a = 0; a < 2; a++)
        #pragma unroll
        for (int b = 0; b < 8; b++)
            #pragma unroll
            for (int c = 0; c < 4; c++) acc[a][b][c] = 0.f;

    const int grp = lane >> 3, r8 = lane & 7;
    const int rowoff = ((grp & 1) << 3) + r8;
    const int cg = grp >> 1;
    int offA[2], swA[2], offB[4], swB[4];
    #pragma unroll
    for (int tm = 0; tm < 2; tm++) {
        int r = warp_m * 32 + tm * 16 + rowoff;
        offA[tm] = r * 64; swA[tm] = (r >> 1) & 3;
    }
    #pragma unroll
    for (int p = 0; p < 4; p++) {
        int r = warp_n * 64 + p * 16 + rowoff;
        offB[p] = r * 64; swB[p] = (r >> 1) & 3;
    }

    const int NIT = Kd >> 5;

    auto load_stage = [&](int st, int k0) {
        uint32_t stb = sb + st * STAGE_B;
        #pragma unroll
        for (int i = 0; i < 4; i++) {
            int plane = i >> 1;
            int r = ((i & 1) << 6) + lr;
            uint32_t dst = stb + plane * 8192 + r * 64 + ((lc ^ ((r >> 1) & 3)) << 4);
            const char* src = (plane == 0)
                ? (const char*)(A + (size_t)(m0 + r) * Kd + k0 + lc * 8)
                : (const char*)(B + (size_t)(n0 + r) * Kd + k0 + lc * 8);
            cp_async16(dst, src);
        }
    };

    #pragma unroll
    for (int s = 0; s < NSTAGE; s++) {
        load_stage(s, s * 32);
        CP_COMMIT();
    }

    for (int it = 0; it < NIT; it++) {
        CP_WAIT2();
        __syncthreads();
        const int st = it % NSTAGE;
        const uint32_t stb = sb + st * STAGE_B;

        #pragma unroll
        for (int ks = 0; ks < 2; ks++) {
            uint32_t ah[2][4], bh[4][4];
            #pragma unroll
            for (int tm = 0; tm < 2; tm++) {
                uint32_t colA = (uint32_t)((((ks << 1) | cg) ^ swA[tm]) << 4);
                ldm_x4(ah[tm], stb + offA[tm] + colA);
            }
            #pragma unroll
            for (int p = 0; p < 4; p++) {
                uint32_t colB = (uint32_t)((((ks << 1) | cg) ^ swB[p]) << 4);
                ldm_x4(bh[p], stb + 8192 + offB[p] + colB);
            }
            #pragma unroll
            for (int tm = 0; tm < 2; tm++)
                #pragma unroll
                for (int tn = 0; tn < 8; tn++) {
                    int p = tn >> 1, o = tn & 1;
                    mma16816(acc[tm][tn], ah[tm], bh[p][o], bh[p][2 + o]);
                }
        }
        __syncthreads();

        int nxt = it + NSTAGE;
        if (nxt < NIT) load_stage(st, nxt * 32);
        CP_COMMIT();
    }

    // ---------------- epilogue ----------------
    const int qr = lane >> 2;
    const int qc = (lane & 3) * 2;
    #pragma unroll
    for (int tm = 0; tm < 2; tm++) {
        int mb = m0 + warp_m * 32 + tm * 16;
        #pragma unroll
        for (int tn = 0; tn < 8; tn++) {
            int n = n0 + warp_n * 64 + tn * 8 + qc;
            float bx = bias[n], by = bias[n + 1];
            #pragma unroll
            for (int half = 0; half < 2; half++) {
                int m = mb + qr + half * 8;
                float vx = acc[tm][tn][half * 2 + 0] + bx;
                float vy = acc[tm][tn][half * 2 + 1] + by;
                size_t o = (size_t)m * N + n;
                if (MODE == 1) {
                    __half2 w;
                    w.x = __float2half(fmaxf(vx, 0.f));
                    w.y = __float2half(fmaxf(vy, 0.f));
                    *(__half2*)(Oh + o) = w;
                } else if (MODE == 2) {
                    float sx = 1.f / (1.f + __expf(-vx));
                    float sy = 1.f / (1.f + __expf(-vy));
                    __half2 tv = *(const __half2*)(X + o);
                    __half2 w;
                    w.x = __float2half(__half2float(tv.x) * sx);
                    w.y = __float2half(__half2float(tv.y) * sy);
                    *(__half2*)(Oh + o) = w;
                } else {
                    float2 w; w.x = vx; w.y = vy;
                    *(float2*)(Of + o) = w;
                }
            }
        }
    }
}

// ---------------- host launch ----------------
extern "C" void kernel_launch(void* const* d_in, const int* in_sizes, int n_in,
                              void* d_out, int out_size)
{
    const float* x  = (const float*)d_in[0];
    const float* W1 = (const float*)d_in[1];
    const float* b1 = (const float*)d_in[2];
    const float* W2 = (const float*)d_in[3];
    const float* b2 = (const float*)d_in[4];
    const float* W3 = (const float*)d_in[5];
    const float* b3 = (const float*)d_in[6];
    float* out = (float*)d_out;

    __half *pt, *ph, *pp, *w1, *w2, *w3;
    cudaGetSymbolAddress((void**)&pt, g_t);
    cudaGetSymbolAddress((void**)&ph, g_h);
    cudaGetSymbolAddress((void**)&pp, g_p);
    cudaGetSymbolAddress((void**)&w1, g_w1);
    cudaGetSymbolAddress((void**)&w2, g_w2);
    cudaGetSymbolAddress((void**)&w3, g_w3);

    cudaFuncSetAttribute(gemm_mma<1>, cudaFuncAttributeMaxDynamicSharedMemorySize, SMEM_BYTES);
    cudaFuncSetAttribute(gemm_mma<2>, cudaFuncAttributeMaxDynamicSharedMemorySize, SMEM_BYTES);
    cudaFuncSetAttribute(gemm_mma<3>, cudaFuncAttributeMaxDynamicSharedMemorySize, SMEM_BYTES);

    unfold_tiled<<<dim3(4, 56, 8), 256>>>(x, pt);
    wtrans_all<<<3 * 1152, 256>>>(W1, W2, W3, w1, w2, w3);

    // K1: h = relu(t @ W1 + b1)        [25088 x 256],  K=2304
    gemm_mma<1><<<dim3(CDIM / 128, L_TOTAL / 128), 256, SMEM_BYTES>>>(
        pt, w1, b1, nullptr, ph, nullptr, L_TOTAL, CDIM, DDIM);
    // K2: p = t * sigmoid(h @ W2 + b2) [25088 x 2304], K=256
    gemm_mma<2><<<dim3(DDIM / 128, L_TOTAL / 128), 256, SMEM_BYTES>>>(
        ph, w2, b2, pt, pp, nullptr, L_TOTAL, DDIM, CDIM);
    // K3: out = p @ W3 + b3            [25088 x 256],  K=2304
    gemm_mma<3><<<dim3(CDIM / 128, L_TOTAL / 128), 256, SMEM_BYTES>>>(
        pp, w3, b3, nullptr, nullptr, out, L_TOTAL, CDIM, DDIM);
}